// round 12
// baseline (speedup 1.0000x reference)
#include <cuda_runtime.h>
#include <cuda_bf16.h>
#include <math.h>
#include <stdint.h>

// Problem dims (fixed by the dataset)
#define NN 8192
#define DD 1024
#define HH 4096
#define KK 4096   // codebook

// ---------------- scratch (static __device__, allocation-free) ----------------
__device__ float g_hcat[(size_t)NN * 2 * HH];   // [8192, 8192]
__device__ float g_h2[(size_t)NN * HH];         // [8192, 4096] (reused for scores)
__device__ float g_h3[(size_t)NN * HH];         // [8192, 4096]
__device__ float g_z[(size_t)NN * DD];          // [8192, 1024]
__device__ float g_e2[KK];
__device__ int   g_idx[NN];

// ---------------- helpers ----------------
__device__ __forceinline__ uint32_t smem_u32(const void* p) {
    uint32_t a;
    asm("{ .reg .u64 t; cvta.to.shared.u64 t, %1; cvt.u32.u64 %0, t; }"
        : "=r"(a) : "l"(p));
    return a;
}
__device__ __forceinline__ void cp_async16(uint32_t saddr, const void* gaddr) {
    asm volatile("cp.async.cg.shared.global [%0], [%1], 16;"
                 :: "r"(saddr), "l"(gaddr) : "memory");
}
#define CP_COMMIT() asm volatile("cp.async.commit_group;" ::: "memory")
#define CP_WAIT1()  asm volatile("cp.async.wait_group 1;" ::: "memory")

// ============================ FFMA GEMM (cp.async, k-major) ===================
// C[m,n] = act( sum_k A[m,k]*B[n,k] + bias[n] ),  A:[M,K], B:[N,K] row-major.
// CTA tile 256x128, 256 threads, thread tile 16x8 (warp 64x64, lanes 4ty x 8tx).
// Smem is k-major (row = 16 k-floats, XOR-swizzled per 16B quad) so cp.async
// stages tiles directly (no STS, no transpose regs). Fragments are float4 over
// k; each acc element still sums k strictly ascending via scalar fmaf ->
// bit-identical to rounds 1/7/9/10 (rel_err 6.29e-8). 3-stage pipeline,
// one commit per chunk, cp.asyncs spread across the q-subloops.
#define BM 256
#define BN 128
#define BK 16
#define TM 16
#define TN 8
#define A_ST (BM * BK)            // 4096 floats per A stage
#define B_ST (BN * BK)            // 2048 floats per B stage
#define STG_F (A_ST + B_ST)       // 6144 floats = 24 KB
#define GSMEM_BYTES (3 * STG_F * 4)   // 73728

// ACT: 0=bias  1=fourier(bias+acc)  2=cat raw+fourier (ldc=2N)  3=score bias-2*acc
template <int ACT>
__global__ __launch_bounds__(256, 1)
void gemm_ca(const float* __restrict__ A, const float* __restrict__ B,
             const float* __restrict__ bias, float* __restrict__ C,
             int M, int N, int K, int ldc)
{
    extern __shared__ float sm[];
    const uint32_t sb = smem_u32(sm);
    const int tid  = threadIdx.x;
    const int lane = tid & 31;
    const int wid  = tid >> 5;
    const int ty = lane >> 3;           // 0..3
    const int tx = lane & 7;            // 0..7
    const int wm = (wid >> 1) * 64;     // 4 warp-rows
    const int wn = (wid & 1) * 64;      // 2 warp-cols
    const int m0 = blockIdx.y * BM;
    const int n0 = blockIdx.x * BN;

    // ---- cp.async loader mapping: lq = 16B quad (4 k's), lr = base row ----
    const int lq = tid & 3;
    const int lr = tid >> 2;            // 0..63
    const float* apg[4]; uint32_t aoff[4];
#pragma unroll
    for (int p = 0; p < 4; p++) {
        const int r = lr + p * 64;      // A rows 0..255
        apg[p] = A + (size_t)(m0 + r) * K + lq * 4;
        aoff[p] = (uint32_t)((r * BK + ((lq ^ ((r >> 4) & 3)) * 4)) * 4);
    }
    const float* bpg[2]; uint32_t boff[2];
#pragma unroll
    for (int p = 0; p < 2; p++) {
        const int r = lr + p * 64;      // B rows 0..127
        bpg[p] = B + (size_t)(n0 + r) * K + lq * 4;
        boff[p] = (uint32_t)((A_ST + r * BK + ((lq ^ ((r >> 3) & 3)) * 4)) * 4);
    }

    const int nk = K / BK;

    // ---- prologue: stage chunks 0 and 1 ----
#pragma unroll
    for (int c = 0; c < 2; c++) {
        const uint32_t st = sb + c * (STG_F * 4);
#pragma unroll
        for (int p = 0; p < 4; p++) cp_async16(st + aoff[p], apg[p] + (size_t)c * BK);
#pragma unroll
        for (int p = 0; p < 2; p++) cp_async16(st + boff[p], bpg[p] + (size_t)c * BK);
        CP_COMMIT();
    }

    float acc[TM][TN];
#pragma unroll
    for (int i = 0; i < TM; i++)
#pragma unroll
        for (int j = 0; j < TN; j++) acc[i][j] = 0.f;

    int stage = 0;
    for (int c = 0; c < nk; c++) {
        CP_WAIT1();          // chunk c's group complete (c+1 may be in flight)
        __syncthreads();     // visible to all warps; write-stage fully consumed

        const float* as = sm + stage * STG_F;
        const float* bs = as + A_ST;
        int ws = stage + 2; if (ws >= 3) ws -= 3;         // stage for chunk c+2
        const uint32_t wst = sb + ws * (STG_F * 4);
        const bool ld = (c + 2 < nk);
        const size_t ko = (size_t)(c + 2) * BK;

#pragma unroll
        for (int q = 0; q < 4; q++) {
            // B fragments (float4 over k)
            float4 bf[TN];
#pragma unroll
            for (int j = 0; j < TN; j++) {
                const int n = wn + tx * TN + j;
                bf[j] = *(const float4*)&bs[n * BK + ((q ^ ((n >> 3) & 3)) * 4)];
            }
            // A fragments in two halves (register pressure)
#pragma unroll
            for (int h = 0; h < 2; h++) {
                float4 af[8];
#pragma unroll
                for (int u = 0; u < 8; u++) {
                    const int m = wm + ty * TM + h * 8 + u;
                    af[u] = *(const float4*)&as[m * BK + ((q ^ ((m >> 4) & 3)) * 4)];
                }
#pragma unroll
                for (int u = 0; u < 8; u++) {
                    const int i = h * 8 + u;
#pragma unroll
                    for (int j = 0; j < TN; j++) {
                        acc[i][j] = fmaf(af[u].x, bf[j].x, acc[i][j]);
                        acc[i][j] = fmaf(af[u].y, bf[j].y, acc[i][j]);
                        acc[i][j] = fmaf(af[u].z, bf[j].z, acc[i][j]);
                        acc[i][j] = fmaf(af[u].w, bf[j].w, acc[i][j]);
                    }
                }
            }
            // spread staging of chunk c+2
            if (q == 0) {
                if (ld) { cp_async16(wst + aoff[0], apg[0] + ko);
                          cp_async16(wst + aoff[1], apg[1] + ko); }
            } else if (q == 1) {
                if (ld) { cp_async16(wst + aoff[2], apg[2] + ko);
                          cp_async16(wst + aoff[3], apg[3] + ko); }
            } else if (q == 2) {
                if (ld) { cp_async16(wst + boff[0], bpg[0] + ko);
                          cp_async16(wst + boff[1], bpg[1] + ko); }
                CP_COMMIT();   // unconditional: keeps group counting uniform
            }
        }
        stage++; if (stage == 3) stage = 0;
    }

    // ---- epilogue (identical expressions to rounds 1/7/9/10) ----
#pragma unroll
    for (int i = 0; i < TM; i++) {
        const int m = m0 + wm + ty * TM + i;
        float* crow = C + (size_t)m * ldc;
#pragma unroll
        for (int j = 0; j < TN; j++) {
            const int n = n0 + wn + tx * TN + j;
            const float s = acc[i][j];
            if (ACT == 0) {
                crow[n] = s + bias[n];
            } else if (ACT == 1) {
                const float v = s + bias[n];
                crow[n] = (n & 1) ? cosf(v) : sinf(v);
            } else if (ACT == 2) {
                const float v = s + bias[n];
                crow[n] = v;
                crow[N + n] = (n & 1) ? cosf(v) : sinf(v);
            } else { // 3: score
                crow[n] = bias[n] - 2.0f * s;
            }
        }
    }
}

// ---------------- e2[k] = ||emb[k]||^2 ----------------
__global__ void e2_kernel(const float* __restrict__ emb, float* __restrict__ e2)
{
    __shared__ float red[256];
    const int k = blockIdx.x;
    const float* row = emb + (size_t)k * DD;
    float s = 0.f;
    for (int d = threadIdx.x; d < DD; d += 256) { float v = row[d]; s += v * v; }
    red[threadIdx.x] = s;
    __syncthreads();
    for (int o = 128; o > 0; o >>= 1) {
        if (threadIdx.x < o) red[threadIdx.x] += red[threadIdx.x + o];
        __syncthreads();
    }
    if (threadIdx.x == 0) e2[k] = red[0];
}

// ---------------- per-row argmin over K scores (first-index tie-break) -------
__global__ void argmin_kernel(const float* __restrict__ scores, int* __restrict__ idx)
{
    __shared__ float bv[256];
    __shared__ int   bi[256];
    const int n = blockIdx.x;
    const float* row = scores + (size_t)n * KK;
    float best = 3.4e38f;
    int besti = 0;
    for (int k = threadIdx.x; k < KK; k += 256) {
        float v = row[k];
        if (v < best) { best = v; besti = k; }
    }
    bv[threadIdx.x] = best;
    bi[threadIdx.x] = besti;
    __syncthreads();
    for (int o = 128; o > 0; o >>= 1) {
        if (threadIdx.x < o) {
            float vo = bv[threadIdx.x + o];
            int   io = bi[threadIdx.x + o];
            if (vo < bv[threadIdx.x] ||
                (vo == bv[threadIdx.x] && io < bi[threadIdx.x])) {
                bv[threadIdx.x] = vo; bi[threadIdx.x] = io;
            }
        }
        __syncthreads();
    }
    if (threadIdx.x == 0) idx[n] = bi[0];
}

// ---------------- mueller hash (numpy int64 wraparound semantics) ------------
__device__ __forceinline__ long long mueller_hash(long long x)
{
    const unsigned long long C = 73244475ull;
    x = (long long)((unsigned long long)((x >> 16) ^ x) * C);
    x = (long long)((unsigned long long)((x >> 16) ^ x) * C);
    return (x >> 16) ^ x;
}

// ---------------- quantize: out[n] = sum_{i=1..3} emb[hash(idx+i*K)&(K-1)]/3 --
__global__ void quant_kernel(const float* __restrict__ emb,
                             const int* __restrict__ idx,
                             float* __restrict__ out)
{
    const int n = blockIdx.x;
    const long long id = (long long)idx[n];
    int s0 = (int)(mueller_hash(id + 1LL * KK) & (long long)(KK - 1));
    int s1 = (int)(mueller_hash(id + 2LL * KK) & (long long)(KK - 1));
    int s2 = (int)(mueller_hash(id + 3LL * KK) & (long long)(KK - 1));
    const float4* e0 = (const float4*)(emb + (size_t)s0 * DD);
    const float4* e1 = (const float4*)(emb + (size_t)s1 * DD);
    const float4* e2p = (const float4*)(emb + (size_t)s2 * DD);
    float4* o = (float4*)(out + (size_t)n * DD);
    const int d = threadIdx.x;
    float4 a = e0[d], b = e1[d], c = e2p[d];
    float4 r;
    r.x = (a.x / 3.0f + b.x / 3.0f) + c.x / 3.0f;
    r.y = (a.y / 3.0f + b.y / 3.0f) + c.y / 3.0f;
    r.z = (a.z / 3.0f + b.z / 3.0f) + c.z / 3.0f;
    r.w = (a.w / 3.0f + b.w / 3.0f) + c.w / 3.0f;
    o[d] = r;
}

// ---------------- host launcher ----------------
extern "C" void kernel_launch(void* const* d_in, const int* in_sizes, int n_in,
                              void* d_out, int out_size)
{
    const float* x   = (const float*)d_in[0];
    const float* w1  = (const float*)d_in[1];
    const float* b1  = (const float*)d_in[2];
    const float* w2  = (const float*)d_in[3];
    const float* b2  = (const float*)d_in[4];
    const float* w3  = (const float*)d_in[5];
    const float* b3  = (const float*)d_in[6];
    const float* w4  = (const float*)d_in[7];
    const float* b4  = (const float*)d_in[8];
    const float* emb = (const float*)d_in[9];
    float* out = (float*)d_out;

    float *hcat, *h2, *h3, *z, *e2d;
    int* idx;
    cudaGetSymbolAddress((void**)&hcat, g_hcat);
    cudaGetSymbolAddress((void**)&h2,   g_h2);
    cudaGetSymbolAddress((void**)&h3,   g_h3);
    cudaGetSymbolAddress((void**)&z,    g_z);
    cudaGetSymbolAddress((void**)&e2d,  g_e2);
    cudaGetSymbolAddress((void**)&idx,  g_idx);

    cudaFuncSetAttribute(gemm_ca<0>, cudaFuncAttributeMaxDynamicSharedMemorySize, GSMEM_BYTES);
    cudaFuncSetAttribute(gemm_ca<1>, cudaFuncAttributeMaxDynamicSharedMemorySize, GSMEM_BYTES);
    cudaFuncSetAttribute(gemm_ca<2>, cudaFuncAttributeMaxDynamicSharedMemorySize, GSMEM_BYTES);
    cudaFuncSetAttribute(gemm_ca<3>, cudaFuncAttributeMaxDynamicSharedMemorySize, GSMEM_BYTES);

    e2_kernel<<<KK, 256>>>(emb, e2d);

    // G1: hcat = [h1, fourier(h1)], h1 = x @ w1.T + b1
    gemm_ca<2><<<dim3(HH / BN, NN / BM), 256, GSMEM_BYTES>>>(
        x, w1, b1, hcat, NN, HH, DD, 2 * HH);
    // G2: h2 = fourier(hcat @ w2.T + b2)
    gemm_ca<1><<<dim3(HH / BN, NN / BM), 256, GSMEM_BYTES>>>(
        hcat, w2, b2, h2, NN, HH, 2 * HH, HH);
    // G3: h3 = fourier(h2 @ w3.T + b3)
    gemm_ca<1><<<dim3(HH / BN, NN / BM), 256, GSMEM_BYTES>>>(
        h2, w3, b3, h3, NN, HH, HH, HH);
    // G4: z = h3 @ w4.T + b4
    gemm_ca<0><<<dim3(DD / BN, NN / BM), 256, GSMEM_BYTES>>>(
        h3, w4, b4, z, NN, DD, HH, DD);
    // G5: scores = e2[k] - 2 * z @ emb.T  (reuse h2)
    gemm_ca<3><<<dim3(KK / BN, NN / BM), 256, GSMEM_BYTES>>>(
        z, emb, e2d, h2, NN, KK, DD, KK);

    argmin_kernel<<<NN, 256>>>(h2, idx);
    quant_kernel<<<NN, 256>>>(emb, idx, out);
}

// round 13
// speedup vs baseline: 1.3299x; 1.3299x over previous
#include <cuda_runtime.h>
#include <cuda_bf16.h>
#include <math.h>
#include <stdint.h>

// Problem dims (fixed by the dataset)
#define NN 8192
#define DD 1024
#define HH 4096
#define KK 4096   // codebook

// ---------------- scratch (static __device__, allocation-free) ----------------
__device__ float g_hcat[(size_t)NN * 2 * HH];   // [8192, 8192]
__device__ float g_h2[(size_t)NN * HH];         // [8192, 4096] (reused for scores)
__device__ float g_h3[(size_t)NN * HH];         // [8192, 4096]
__device__ float g_z[(size_t)NN * DD];          // [8192, 1024]
__device__ float g_e2[KK];
__device__ int   g_idx[NN];

// ---------------- packed f32x2 helpers ----------------
__device__ __forceinline__ void fma2(unsigned long long& c,
                                     unsigned long long a,
                                     unsigned long long b) {
    asm("fma.rn.f32x2 %0, %1, %2, %0;" : "+l"(c) : "l"(a), "l"(b));
}
__device__ __forceinline__ unsigned long long pack2(float lo, float hi) {
    unsigned long long r;
    asm("mov.b64 %0, {%1, %2};" : "=l"(r) : "f"(lo), "f"(hi));
    return r;
}
__device__ __forceinline__ float lo_f(unsigned long long v) {
    float lo, hi;
    asm("mov.b64 {%0, %1}, %2;" : "=f"(lo), "=f"(hi) : "l"(v));
    return lo;
}
__device__ __forceinline__ float hi_f(unsigned long long v) {
    float lo, hi;
    asm("mov.b64 {%0, %1}, %2;" : "=f"(lo), "=f"(hi) : "l"(v));
    return hi;
}

// ============================ FFMA2 GEMM (fat tile, spread loader) ============
// C[m,n] = act( sum_k A[m,k]*B[n,k] + bias[n] ),  A:[M,K], B:[N,K] row-major.
// CTA tile 256x128, 256 threads, thread tile 16x8 held as 16x4 f32x2 pairs.
// fma.rn.f32x2 = two independent IEEE fma.rn.f32 lanes; each output element
// keeps a single accumulator with strictly ascending k -> bit-identical to
// rounds 1/7/9/10 (rel_err 6.29e-8). One issue slot now feeds 2 fma-pipe
// slots, creating issue slack that absorbs LDS/LDG/barrier stalls.
// Register-staged double buffer; STS/LDG staging spread across kk (round 10).
#define BM 256
#define BN 128
#define BK 16
#define TM 16
#define TN 8

// ACT: 0=bias  1=fourier(bias+acc)  2=cat raw+fourier (ldc=2N)  3=score bias-2*acc
template <int ACT>
__global__ __launch_bounds__(256, 1)
void gemm_f2b(const float* __restrict__ A, const float* __restrict__ B,
              const float* __restrict__ bias, float* __restrict__ C,
              int M, int N, int K, int ldc)
{
    __shared__ float As[2][BK][BM];   // 32 KB
    __shared__ float Bs[2][BK][BN];   // 16 KB

    const int tid  = threadIdx.x;
    const int lane = tid & 31;
    const int wid  = tid >> 5;
    const int ty = lane >> 3;           // 0..3  (row groups of 16)
    const int tx = lane & 7;            // 0..7  (col groups of 8)
    const int wm = (wid >> 1) * 64;     // 4 warp-rows
    const int wn = (wid & 1) * 64;      // 2 warp-cols
    const int m0 = blockIdx.y * BM;
    const int n0 = blockIdx.x * BN;

    // loader mapping: A: thread tid owns full row tid (16 floats)
    //                 B: 2 threads per row, 8 k's each
    const int blr = tid >> 1;
    const int blk = (tid & 1) * 8;
    const float* ag = A + (size_t)(m0 + tid) * K;
    const float* bg = B + (size_t)(n0 + blr) * K + blk;

    const int nk = K / BK;

    // ---- prologue: LDG chunk0 -> STS stage0 ; LDG chunk1 -> regs ----
    float4 a0, a1, a2, a3, b0, b1;
    a0 = *(const float4*)(ag);      a1 = *(const float4*)(ag + 4);
    a2 = *(const float4*)(ag + 8);  a3 = *(const float4*)(ag + 12);
    b0 = *(const float4*)(bg);      b1 = *(const float4*)(bg + 4);
    {
        As[0][ 0][tid] = a0.x; As[0][ 1][tid] = a0.y;
        As[0][ 2][tid] = a0.z; As[0][ 3][tid] = a0.w;
        As[0][ 4][tid] = a1.x; As[0][ 5][tid] = a1.y;
        As[0][ 6][tid] = a1.z; As[0][ 7][tid] = a1.w;
        As[0][ 8][tid] = a2.x; As[0][ 9][tid] = a2.y;
        As[0][10][tid] = a2.z; As[0][11][tid] = a2.w;
        As[0][12][tid] = a3.x; As[0][13][tid] = a3.y;
        As[0][14][tid] = a3.z; As[0][15][tid] = a3.w;
        Bs[0][blk + 0][blr] = b0.x; Bs[0][blk + 1][blr] = b0.y;
        Bs[0][blk + 2][blr] = b0.z; Bs[0][blk + 3][blr] = b0.w;
        Bs[0][blk + 4][blr] = b1.x; Bs[0][blk + 5][blr] = b1.y;
        Bs[0][blk + 6][blr] = b1.z; Bs[0][blk + 7][blr] = b1.w;
    }
    if (nk > 1) {
        a0 = *(const float4*)(ag + BK);      a1 = *(const float4*)(ag + BK + 4);
        a2 = *(const float4*)(ag + BK + 8);  a3 = *(const float4*)(ag + BK + 12);
        b0 = *(const float4*)(bg + BK);      b1 = *(const float4*)(bg + BK + 4);
    }

    // acc pairs: acc2[i][j] = (acc[i][2j], acc[i][2j+1])
    unsigned long long acc2[TM][TN / 2];
#pragma unroll
    for (int i = 0; i < TM; i++)
#pragma unroll
        for (int j = 0; j < TN / 2; j++) acc2[i][j] = 0ull;

    for (int c = 0; c < nk; c++) {
        __syncthreads();   // STS(c) visible; stage (c+1)&1 free for writing

        const int s = (c + 1) & 1;                 // stage being filled
        const bool do_sts = (c + 1 < nk);
        const bool do_ldg = (c + 2 < nk);
        const float* an = ag + (size_t)(c + 2) * BK;   // LDG source (chunk c+2)
        const float* bn = bg + (size_t)(c + 2) * BK;

        const float (*as)[BM] = As[c & 1];
        const float (*bs)[BN] = Bs[c & 1];

#pragma unroll
        for (int kk = 0; kk < BK; kk++) {
            // ---- compute kk ----
            const float* arow = &as[kk][wm + ty * TM];
            const float* brow = &bs[kk][wn + tx * TN];
            float4 af0 = *(const float4*)(arow);
            float4 af1 = *(const float4*)(arow + 4);
            float4 af2 = *(const float4*)(arow + 8);
            float4 af3 = *(const float4*)(arow + 12);
            float4 bf0 = *(const float4*)(brow);
            float4 bf1 = *(const float4*)(brow + 4);
            // B pairs (adjacent n): free pairing from LDS.128 registers
            unsigned long long B2[TN / 2];
            B2[0] = pack2(bf0.x, bf0.y); B2[1] = pack2(bf0.z, bf0.w);
            B2[2] = pack2(bf1.x, bf1.y); B2[3] = pack2(bf1.z, bf1.w);
            // A scalars duplicated into both halves
            float af[TM] = {af0.x, af0.y, af0.z, af0.w, af1.x, af1.y, af1.z, af1.w,
                            af2.x, af2.y, af2.z, af2.w, af3.x, af3.y, af3.z, af3.w};
#pragma unroll
            for (int i = 0; i < TM; i++) {
                const unsigned long long A2 = pack2(af[i], af[i]);
#pragma unroll
                for (int j = 0; j < TN / 2; j++)
                    fma2(acc2[i][j], A2, B2[j]);
            }

            // ---- interleaved staging: retire one quad (STS then reload) ----
            if (kk == 1) {
                if (do_sts) {
                    As[s][0][tid] = a0.x; As[s][1][tid] = a0.y;
                    As[s][2][tid] = a0.z; As[s][3][tid] = a0.w;
                }
                if (do_ldg) a0 = *(const float4*)(an);
            } else if (kk == 3) {
                if (do_sts) {
                    As[s][4][tid] = a1.x; As[s][5][tid] = a1.y;
                    As[s][6][tid] = a1.z; As[s][7][tid] = a1.w;
                }
                if (do_ldg) a1 = *(const float4*)(an + 4);
            } else if (kk == 5) {
                if (do_sts) {
                    As[s][ 8][tid] = a2.x; As[s][ 9][tid] = a2.y;
                    As[s][10][tid] = a2.z; As[s][11][tid] = a2.w;
                }
                if (do_ldg) a2 = *(const float4*)(an + 8);
            } else if (kk == 7) {
                if (do_sts) {
                    As[s][12][tid] = a3.x; As[s][13][tid] = a3.y;
                    As[s][14][tid] = a3.z; As[s][15][tid] = a3.w;
                }
                if (do_ldg) a3 = *(const float4*)(an + 12);
            } else if (kk == 9) {
                if (do_sts) {
                    Bs[s][blk + 0][blr] = b0.x; Bs[s][blk + 1][blr] = b0.y;
                    Bs[s][blk + 2][blr] = b0.z; Bs[s][blk + 3][blr] = b0.w;
                }
                if (do_ldg) b0 = *(const float4*)(bn);
            } else if (kk == 11) {
                if (do_sts) {
                    Bs[s][blk + 4][blr] = b1.x; Bs[s][blk + 5][blr] = b1.y;
                    Bs[s][blk + 6][blr] = b1.z; Bs[s][blk + 7][blr] = b1.w;
                }
                if (do_ldg) b1 = *(const float4*)(bn + 4);
            }
        }
    }

    // ---- epilogue (identical expressions to rounds 1/7/9/10) ----
#pragma unroll
    for (int i = 0; i < TM; i++) {
        const int m = m0 + wm + ty * TM + i;
        float* crow = C + (size_t)m * ldc;
#pragma unroll
        for (int j = 0; j < TN / 2; j++) {
            const int n = n0 + wn + tx * TN + 2 * j;   // even column
            const float s0 = lo_f(acc2[i][j]);
            const float s1 = hi_f(acc2[i][j]);
            if (ACT == 0) {
                crow[n]     = s0 + bias[n];
                crow[n + 1] = s1 + bias[n + 1];
            } else if (ACT == 1) {
                const float v0 = s0 + bias[n];
                const float v1 = s1 + bias[n + 1];
                crow[n]     = sinf(v0);   // n even -> sin
                crow[n + 1] = cosf(v1);   // n+1 odd -> cos
            } else if (ACT == 2) {
                const float v0 = s0 + bias[n];
                const float v1 = s1 + bias[n + 1];
                crow[n]         = v0;
                crow[n + 1]     = v1;
                crow[N + n]     = sinf(v0);
                crow[N + n + 1] = cosf(v1);
            } else { // 3: score
                crow[n]     = bias[n]     - 2.0f * s0;
                crow[n + 1] = bias[n + 1] - 2.0f * s1;
            }
        }
    }
}

// ---------------- e2[k] = ||emb[k]||^2 ----------------
__global__ void e2_kernel(const float* __restrict__ emb, float* __restrict__ e2)
{
    __shared__ float red[256];
    const int k = blockIdx.x;
    const float* row = emb + (size_t)k * DD;
    float s = 0.f;
    for (int d = threadIdx.x; d < DD; d += 256) { float v = row[d]; s += v * v; }
    red[threadIdx.x] = s;
    __syncthreads();
    for (int o = 128; o > 0; o >>= 1) {
        if (threadIdx.x < o) red[threadIdx.x] += red[threadIdx.x + o];
        __syncthreads();
    }
    if (threadIdx.x == 0) e2[k] = red[0];
}

// ---------------- per-row argmin over K scores (first-index tie-break) -------
__global__ void argmin_kernel(const float* __restrict__ scores, int* __restrict__ idx)
{
    __shared__ float bv[256];
    __shared__ int   bi[256];
    const int n = blockIdx.x;
    const float* row = scores + (size_t)n * KK;
    float best = 3.4e38f;
    int besti = 0;
    for (int k = threadIdx.x; k < KK; k += 256) {
        float v = row[k];
        if (v < best) { best = v; besti = k; }
    }
    bv[threadIdx.x] = best;
    bi[threadIdx.x] = besti;
    __syncthreads();
    for (int o = 128; o > 0; o >>= 1) {
        if (threadIdx.x < o) {
            float vo = bv[threadIdx.x + o];
            int   io = bi[threadIdx.x + o];
            if (vo < bv[threadIdx.x] ||
                (vo == bv[threadIdx.x] && io < bi[threadIdx.x])) {
                bv[threadIdx.x] = vo; bi[threadIdx.x] = io;
            }
        }
        __syncthreads();
    }
    if (threadIdx.x == 0) idx[n] = bi[0];
}

// ---------------- mueller hash (numpy int64 wraparound semantics) ------------
__device__ __forceinline__ long long mueller_hash(long long x)
{
    const unsigned long long C = 73244475ull;
    x = (long long)((unsigned long long)((x >> 16) ^ x) * C);
    x = (long long)((unsigned long long)((x >> 16) ^ x) * C);
    return (x >> 16) ^ x;
}

// ---------------- quantize: out[n] = sum_{i=1..3} emb[hash(idx+i*K)&(K-1)]/3 --
__global__ void quant_kernel(const float* __restrict__ emb,
                             const int* __restrict__ idx,
                             float* __restrict__ out)
{
    const int n = blockIdx.x;
    const long long id = (long long)idx[n];
    int s0 = (int)(mueller_hash(id + 1LL * KK) & (long long)(KK - 1));
    int s1 = (int)(mueller_hash(id + 2LL * KK) & (long long)(KK - 1));
    int s2 = (int)(mueller_hash(id + 3LL * KK) & (long long)(KK - 1));
    const float4* e0 = (const float4*)(emb + (size_t)s0 * DD);
    const float4* e1 = (const float4*)(emb + (size_t)s1 * DD);
    const float4* e2p = (const float4*)(emb + (size_t)s2 * DD);
    float4* o = (float4*)(out + (size_t)n * DD);
    const int d = threadIdx.x;
    float4 a = e0[d], b = e1[d], c = e2p[d];
    float4 r;
    r.x = (a.x / 3.0f + b.x / 3.0f) + c.x / 3.0f;
    r.y = (a.y / 3.0f + b.y / 3.0f) + c.y / 3.0f;
    r.z = (a.z / 3.0f + b.z / 3.0f) + c.z / 3.0f;
    r.w = (a.w / 3.0f + b.w / 3.0f) + c.w / 3.0f;
    o[d] = r;
}

// ---------------- host launcher ----------------
extern "C" void kernel_launch(void* const* d_in, const int* in_sizes, int n_in,
                              void* d_out, int out_size)
{
    const float* x   = (const float*)d_in[0];
    const float* w1  = (const float*)d_in[1];
    const float* b1  = (const float*)d_in[2];
    const float* w2  = (const float*)d_in[3];
    const float* b2  = (const float*)d_in[4];
    const float* w3  = (const float*)d_in[5];
    const float* b3  = (const float*)d_in[6];
    const float* w4  = (const float*)d_in[7];
    const float* b4  = (const float*)d_in[8];
    const float* emb = (const float*)d_in[9];
    float* out = (float*)d_out;

    float *hcat, *h2, *h3, *z, *e2d;
    int* idx;
    cudaGetSymbolAddress((void**)&hcat, g_hcat);
    cudaGetSymbolAddress((void**)&h2,   g_h2);
    cudaGetSymbolAddress((void**)&h3,   g_h3);
    cudaGetSymbolAddress((void**)&z,    g_z);
    cudaGetSymbolAddress((void**)&e2d,  g_e2);
    cudaGetSymbolAddress((void**)&idx,  g_idx);

    e2_kernel<<<KK, 256>>>(emb, e2d);

    // G1: hcat = [h1, fourier(h1)], h1 = x @ w1.T + b1
    gemm_f2b<2><<<dim3(HH / BN, NN / BM), 256>>>(x, w1, b1, hcat, NN, HH, DD, 2 * HH);
    // G2: h2 = fourier(hcat @ w2.T + b2)
    gemm_f2b<1><<<dim3(HH / BN, NN / BM), 256>>>(hcat, w2, b2, h2, NN, HH, 2 * HH, HH);
    // G3: h3 = fourier(h2 @ w3.T + b3)
    gemm_f2b<1><<<dim3(HH / BN, NN / BM), 256>>>(h2, w3, b3, h3, NN, HH, HH, HH);
    // G4: z = h3 @ w4.T + b4
    gemm_f2b<0><<<dim3(DD / BN, NN / BM), 256>>>(h3, w4, b4, z, NN, DD, HH, DD);
    // G5: scores = e2[k] - 2 * z @ emb.T  (reuse h2)
    gemm_f2b<3><<<dim3(KK / BN, NN / BM), 256>>>(z, emb, e2d, h2, NN, KK, DD, KK);

    argmin_kernel<<<NN, 256>>>(h2, idx);
    quant_kernel<<<NN, 256>>>(emb, idx, out);
}

// round 14
// speedup vs baseline: 1.3949x; 1.0488x over previous
#include <cuda_runtime.h>
#include <cuda_bf16.h>
#include <math.h>
#include <stdint.h>

// Problem dims (fixed by the dataset)
#define NN 8192
#define DD 1024
#define HH 4096
#define KK 4096   // codebook

// ---------------- scratch (static __device__, allocation-free) ----------------
__device__ float g_hcat[(size_t)NN * 2 * HH];   // [8192, 8192]
__device__ float g_h2[(size_t)NN * HH];         // [8192, 4096] (reused for scores)
__device__ float g_h3[(size_t)NN * HH];         // [8192, 4096]
__device__ float g_z[(size_t)NN * DD];          // [8192, 1024]
__device__ float g_e2[KK];
__device__ int   g_idx[NN];

// ---------------- packed f32x2 helpers ----------------
__device__ __forceinline__ void fma2(unsigned long long& c,
                                     unsigned long long a,
                                     unsigned long long b) {
    asm("fma.rn.f32x2 %0, %1, %2, %0;" : "+l"(c) : "l"(a), "l"(b));
}
__device__ __forceinline__ unsigned long long pack2(float lo, float hi) {
    unsigned long long r;
    asm("mov.b64 %0, {%1, %2};" : "=l"(r) : "f"(lo), "f"(hi));
    return r;
}
__device__ __forceinline__ float lo_f(unsigned long long v) {
    float lo, hi;
    asm("mov.b64 {%0, %1}, %2;" : "=f"(lo), "=f"(hi) : "l"(v));
    return lo;
}
__device__ __forceinline__ float hi_f(unsigned long long v) {
    float lo, hi;
    asm("mov.b64 {%0, %1}, %2;" : "=f"(lo), "=f"(hi) : "l"(v));
    return hi;
}

// ============================ FFMA2 GEMM (M-paired accumulators) ==============
// C[m,n] = act( sum_k A[m,k]*B[n,k] + bias[n] ),  A:[M,K], B:[N,K] row-major.
// CTA tile 256x128, 256 threads, thread tile 16x8 held as 8 m-pairs x 8 cols.
// Pairing over M: A pairs are adjacent floats in the smem row -> loaded
// directly as 64-bit lanes (no dup MOVs). Only B needs dup-packs (8 per kk).
// fma.rn.f32x2 = two independent IEEE fma.rn.f32 lanes; each output element
// keeps one accumulator with strictly ascending k -> bit-identical to rounds
// 1/7/9/10/13 (rel_err 6.29e-8). Explicit fragment double-buffer hides LDS
// latency; register-staged smem double buffer with spread STS/LDG (round 10).
#define BM 256
#define BN 128
#define BK 16
#define TM 16
#define TN 8

// ACT: 0=bias  1=fourier(bias+acc)  2=cat raw+fourier (ldc=2N)  3=score bias-2*acc
template <int ACT>
__global__ __launch_bounds__(256, 1)
void gemm_f2m(const float* __restrict__ A, const float* __restrict__ B,
              const float* __restrict__ bias, float* __restrict__ C,
              int M, int N, int K, int ldc)
{
    __shared__ float As[2][BK][BM];   // 32 KB
    __shared__ float Bs[2][BK][BN];   // 16 KB

    const int tid  = threadIdx.x;
    const int lane = tid & 31;
    const int wid  = tid >> 5;
    const int ty = lane >> 3;           // 0..3  (row groups of 16)
    const int tx = lane & 7;            // 0..7  (col groups of 8)
    const int wm = (wid >> 1) * 64;     // 4 warp-rows
    const int wn = (wid & 1) * 64;      // 2 warp-cols
    const int m0 = blockIdx.y * BM;
    const int n0 = blockIdx.x * BN;

    // loader mapping: A: thread tid owns full row tid (16 floats)
    //                 B: 2 threads per row, 8 k's each
    const int blr = tid >> 1;
    const int blk = (tid & 1) * 8;
    const float* ag = A + (size_t)(m0 + tid) * K;
    const float* bg = B + (size_t)(n0 + blr) * K + blk;

    const int nk = K / BK;

    // ---- prologue: LDG chunk0 -> STS stage0 ; LDG chunk1 -> regs ----
    float4 a0, a1, a2, a3, b0, b1;
    a0 = *(const float4*)(ag);      a1 = *(const float4*)(ag + 4);
    a2 = *(const float4*)(ag + 8);  a3 = *(const float4*)(ag + 12);
    b0 = *(const float4*)(bg);      b1 = *(const float4*)(bg + 4);
    {
        As[0][ 0][tid] = a0.x; As[0][ 1][tid] = a0.y;
        As[0][ 2][tid] = a0.z; As[0][ 3][tid] = a0.w;
        As[0][ 4][tid] = a1.x; As[0][ 5][tid] = a1.y;
        As[0][ 6][tid] = a1.z; As[0][ 7][tid] = a1.w;
        As[0][ 8][tid] = a2.x; As[0][ 9][tid] = a2.y;
        As[0][10][tid] = a2.z; As[0][11][tid] = a2.w;
        As[0][12][tid] = a3.x; As[0][13][tid] = a3.y;
        As[0][14][tid] = a3.z; As[0][15][tid] = a3.w;
        Bs[0][blk + 0][blr] = b0.x; Bs[0][blk + 1][blr] = b0.y;
        Bs[0][blk + 2][blr] = b0.z; Bs[0][blk + 3][blr] = b0.w;
        Bs[0][blk + 4][blr] = b1.x; Bs[0][blk + 5][blr] = b1.y;
        Bs[0][blk + 6][blr] = b1.z; Bs[0][blk + 7][blr] = b1.w;
    }
    if (nk > 1) {
        a0 = *(const float4*)(ag + BK);      a1 = *(const float4*)(ag + BK + 4);
        a2 = *(const float4*)(ag + BK + 8);  a3 = *(const float4*)(ag + BK + 12);
        b0 = *(const float4*)(bg + BK);      b1 = *(const float4*)(bg + BK + 4);
    }

    // acc pairs over M: acc2[p][j] = (acc[2p][j], acc[2p+1][j])
    unsigned long long acc2[TM / 2][TN];
#pragma unroll
    for (int p = 0; p < TM / 2; p++)
#pragma unroll
        for (int j = 0; j < TN; j++) acc2[p][j] = 0ull;

    for (int c = 0; c < nk; c++) {
        __syncthreads();   // STS(c) visible; stage (c+1)&1 free for writing

        const int s = (c + 1) & 1;                 // stage being filled
        const bool do_sts = (c + 1 < nk);
        const bool do_ldg = (c + 2 < nk);
        const float* an = ag + (size_t)(c + 2) * BK;   // LDG source (chunk c+2)
        const float* bn = bg + (size_t)(c + 2) * BK;

        const float (*as)[BM] = As[c & 1];
        const float (*bs)[BN] = Bs[c & 1];

        // ---- fragment double buffer: load kk=0 ----
        ulonglong2 au[2][4];
        float4     bu[2][2];
        {
            const float* ar = &as[0][wm + ty * TM];
            const float* br = &bs[0][wn + tx * TN];
            au[0][0] = *(const ulonglong2*)(ar);
            au[0][1] = *(const ulonglong2*)(ar + 4);
            au[0][2] = *(const ulonglong2*)(ar + 8);
            au[0][3] = *(const ulonglong2*)(ar + 12);
            bu[0][0] = *(const float4*)(br);
            bu[0][1] = *(const float4*)(br + 4);
        }

#pragma unroll
        for (int kk = 0; kk < BK; kk++) {
            const int cur = kk & 1;
            const int nxt = cur ^ 1;
            // prefetch kk+1 fragments (latency hidden under compute below)
            if (kk + 1 < BK) {
                const float* ar = &as[kk + 1][wm + ty * TM];
                const float* br = &bs[kk + 1][wn + tx * TN];
                au[nxt][0] = *(const ulonglong2*)(ar);
                au[nxt][1] = *(const ulonglong2*)(ar + 4);
                au[nxt][2] = *(const ulonglong2*)(ar + 8);
                au[nxt][3] = *(const ulonglong2*)(ar + 12);
                bu[nxt][0] = *(const float4*)(br);
                bu[nxt][1] = *(const float4*)(br + 4);
            }

            // ---- compute kk ----
            // B dup-packs (8): lane pair (b, b)
            unsigned long long Bd[TN];
            Bd[0] = pack2(bu[cur][0].x, bu[cur][0].x);
            Bd[1] = pack2(bu[cur][0].y, bu[cur][0].y);
            Bd[2] = pack2(bu[cur][0].z, bu[cur][0].z);
            Bd[3] = pack2(bu[cur][0].w, bu[cur][0].w);
            Bd[4] = pack2(bu[cur][1].x, bu[cur][1].x);
            Bd[5] = pack2(bu[cur][1].y, bu[cur][1].y);
            Bd[6] = pack2(bu[cur][1].z, bu[cur][1].z);
            Bd[7] = pack2(bu[cur][1].w, bu[cur][1].w);
            // A pairs (8): adjacent m floats, direct 64-bit lanes (no MOVs)
            unsigned long long Ap[TM / 2];
            Ap[0] = au[cur][0].x; Ap[1] = au[cur][0].y;
            Ap[2] = au[cur][1].x; Ap[3] = au[cur][1].y;
            Ap[4] = au[cur][2].x; Ap[5] = au[cur][2].y;
            Ap[6] = au[cur][3].x; Ap[7] = au[cur][3].y;
#pragma unroll
            for (int p = 0; p < TM / 2; p++)
#pragma unroll
                for (int j = 0; j < TN; j++)
                    fma2(acc2[p][j], Ap[p], Bd[j]);

            // ---- interleaved staging: retire one quad (STS then reload) ----
            if (kk == 1) {
                if (do_sts) {
                    As[s][0][tid] = a0.x; As[s][1][tid] = a0.y;
                    As[s][2][tid] = a0.z; As[s][3][tid] = a0.w;
                }
                if (do_ldg) a0 = *(const float4*)(an);
            } else if (kk == 3) {
                if (do_sts) {
                    As[s][4][tid] = a1.x; As[s][5][tid] = a1.y;
                    As[s][6][tid] = a1.z; As[s][7][tid] = a1.w;
                }
                if (do_ldg) a1 = *(const float4*)(an + 4);
            } else if (kk == 5) {
                if (do_sts) {
                    As[s][ 8][tid] = a2.x; As[s][ 9][tid] = a2.y;
                    As[s][10][tid] = a2.z; As[s][11][tid] = a2.w;
                }
                if (do_ldg) a2 = *(const float4*)(an + 8);
            } else if (kk == 7) {
                if (do_sts) {
                    As[s][12][tid] = a3.x; As[s][13][tid] = a3.y;
                    As[s][14][tid] = a3.z; As[s][15][tid] = a3.w;
                }
                if (do_ldg) a3 = *(const float4*)(an + 12);
            } else if (kk == 9) {
                if (do_sts) {
                    Bs[s][blk + 0][blr] = b0.x; Bs[s][blk + 1][blr] = b0.y;
                    Bs[s][blk + 2][blr] = b0.z; Bs[s][blk + 3][blr] = b0.w;
                }
                if (do_ldg) b0 = *(const float4*)(bn);
            } else if (kk == 11) {
                if (do_sts) {
                    Bs[s][blk + 4][blr] = b1.x; Bs[s][blk + 5][blr] = b1.y;
                    Bs[s][blk + 6][blr] = b1.z; Bs[s][blk + 7][blr] = b1.w;
                }
                if (do_ldg) b1 = *(const float4*)(bn + 4);
            }
        }
    }

    // ---- epilogue (identical expressions to rounds 1/7/9/10/13) ----
#pragma unroll
    for (int p = 0; p < TM / 2; p++) {
        const int me = m0 + wm + ty * TM + 2 * p;   // even row of the pair
        float* crow0 = C + (size_t)me * ldc;
        float* crow1 = C + (size_t)(me + 1) * ldc;
#pragma unroll
        for (int j = 0; j < TN; j++) {
            const int n = n0 + wn + tx * TN + j;
            const float s0 = lo_f(acc2[p][j]);   // row me
            const float s1 = hi_f(acc2[p][j]);   // row me+1
            if (ACT == 0) {
                crow0[n] = s0 + bias[n];
                crow1[n] = s1 + bias[n];
            } else if (ACT == 1) {
                const float v0 = s0 + bias[n];
                const float v1 = s1 + bias[n];
                crow0[n] = (n & 1) ? cosf(v0) : sinf(v0);
                crow1[n] = (n & 1) ? cosf(v1) : sinf(v1);
            } else if (ACT == 2) {
                const float v0 = s0 + bias[n];
                const float v1 = s1 + bias[n];
                crow0[n] = v0;
                crow1[n] = v1;
                crow0[N + n] = (n & 1) ? cosf(v0) : sinf(v0);
                crow1[N + n] = (n & 1) ? cosf(v1) : sinf(v1);
            } else { // 3: score
                crow0[n] = bias[n] - 2.0f * s0;
                crow1[n] = bias[n] - 2.0f * s1;
            }
        }
    }
}

// ---------------- e2[k] = ||emb[k]||^2 ----------------
__global__ void e2_kernel(const float* __restrict__ emb, float* __restrict__ e2)
{
    __shared__ float red[256];
    const int k = blockIdx.x;
    const float* row = emb + (size_t)k * DD;
    float s = 0.f;
    for (int d = threadIdx.x; d < DD; d += 256) { float v = row[d]; s += v * v; }
    red[threadIdx.x] = s;
    __syncthreads();
    for (int o = 128; o > 0; o >>= 1) {
        if (threadIdx.x < o) red[threadIdx.x] += red[threadIdx.x + o];
        __syncthreads();
    }
    if (threadIdx.x == 0) e2[k] = red[0];
}

// ---------------- per-row argmin over K scores (first-index tie-break) -------
__global__ void argmin_kernel(const float* __restrict__ scores, int* __restrict__ idx)
{
    __shared__ float bv[256];
    __shared__ int   bi[256];
    const int n = blockIdx.x;
    const float* row = scores + (size_t)n * KK;
    float best = 3.4e38f;
    int besti = 0;
    for (int k = threadIdx.x; k < KK; k += 256) {
        float v = row[k];
        if (v < best) { best = v; besti = k; }
    }
    bv[threadIdx.x] = best;
    bi[threadIdx.x] = besti;
    __syncthreads();
    for (int o = 128; o > 0; o >>= 1) {
        if (threadIdx.x < o) {
            float vo = bv[threadIdx.x + o];
            int   io = bi[threadIdx.x + o];
            if (vo < bv[threadIdx.x] ||
                (vo == bv[threadIdx.x] && io < bi[threadIdx.x])) {
                bv[threadIdx.x] = vo; bi[threadIdx.x] = io;
            }
        }
        __syncthreads();
    }
    if (threadIdx.x == 0) idx[n] = bi[0];
}

// ---------------- mueller hash (numpy int64 wraparound semantics) ------------
__device__ __forceinline__ long long mueller_hash(long long x)
{
    const unsigned long long C = 73244475ull;
    x = (long long)((unsigned long long)((x >> 16) ^ x) * C);
    x = (long long)((unsigned long long)((x >> 16) ^ x) * C);
    return (x >> 16) ^ x;
}

// ---------------- quantize: out[n] = sum_{i=1..3} emb[hash(idx+i*K)&(K-1)]/3 --
__global__ void quant_kernel(const float* __restrict__ emb,
                             const int* __restrict__ idx,
                             float* __restrict__ out)
{
    const int n = blockIdx.x;
    const long long id = (long long)idx[n];
    int s0 = (int)(mueller_hash(id + 1LL * KK) & (long long)(KK - 1));
    int s1 = (int)(mueller_hash(id + 2LL * KK) & (long long)(KK - 1));
    int s2 = (int)(mueller_hash(id + 3LL * KK) & (long long)(KK - 1));
    const float4* e0 = (const float4*)(emb + (size_t)s0 * DD);
    const float4* e1 = (const float4*)(emb + (size_t)s1 * DD);
    const float4* e2p = (const float4*)(emb + (size_t)s2 * DD);
    float4* o = (float4*)(out + (size_t)n * DD);
    const int d = threadIdx.x;
    float4 a = e0[d], b = e1[d], c = e2p[d];
    float4 r;
    r.x = (a.x / 3.0f + b.x / 3.0f) + c.x / 3.0f;
    r.y = (a.y / 3.0f + b.y / 3.0f) + c.y / 3.0f;
    r.z = (a.z / 3.0f + b.z / 3.0f) + c.z / 3.0f;
    r.w = (a.w / 3.0f + b.w / 3.0f) + c.w / 3.0f;
    o[d] = r;
}

// ---------------- host launcher ----------------
extern "C" void kernel_launch(void* const* d_in, const int* in_sizes, int n_in,
                              void* d_out, int out_size)
{
    const float* x   = (const float*)d_in[0];
    const float* w1  = (const float*)d_in[1];
    const float* b1  = (const float*)d_in[2];
    const float* w2  = (const float*)d_in[3];
    const float* b2  = (const float*)d_in[4];
    const float* w3  = (const float*)d_in[5];
    const float* b3  = (const float*)d_in[6];
    const float* w4  = (const float*)d_in[7];
    const float* b4  = (const float*)d_in[8];
    const float* emb = (const float*)d_in[9];
    float* out = (float*)d_out;

    float *hcat, *h2, *h3, *z, *e2d;
    int* idx;
    cudaGetSymbolAddress((void**)&hcat, g_hcat);
    cudaGetSymbolAddress((void**)&h2,   g_h2);
    cudaGetSymbolAddress((void**)&h3,   g_h3);
    cudaGetSymbolAddress((void**)&z,    g_z);
    cudaGetSymbolAddress((void**)&e2d,  g_e2);
    cudaGetSymbolAddress((void**)&idx,  g_idx);

    e2_kernel<<<KK, 256>>>(emb, e2d);

    // G1: hcat = [h1, fourier(h1)], h1 = x @ w1.T + b1
    gemm_f2m<2><<<dim3(HH / BN, NN / BM), 256>>>(x, w1, b1, hcat, NN, HH, DD, 2 * HH);
    // G2: h2 = fourier(hcat @ w2.T + b2)
    gemm_f2m<1><<<dim3(HH / BN, NN / BM), 256>>>(hcat, w2, b2, h2, NN, HH, 2 * HH, HH);
    // G3: h3 = fourier(h2 @ w3.T + b3)
    gemm_f2m<1><<<dim3(HH / BN, NN / BM), 256>>>(h2, w3, b3, h3, NN, HH, HH, HH);
    // G4: z = h3 @ w4.T + b4
    gemm_f2m<0><<<dim3(DD / BN, NN / BM), 256>>>(h3, w4, b4, z, NN, DD, HH, DD);
    // G5: scores = e2[k] - 2 * z @ emb.T  (reuse h2)
    gemm_f2m<3><<<dim3(KK / BN, NN / BM), 256>>>(z, emb, e2d, h2, NN, KK, DD, KK);

    argmin_kernel<<<NN, 256>>>(h2, idx);
    quant_kernel<<<NN, 256>>>(emb, idx, out);
}